// round 9
// baseline (speedup 1.0000x reference)
#include <cuda_runtime.h>
#include <math.h>

#define B       16
#define N       128
#define NC      80
#define HW0     25600
#define HW1     6400
#define HW2     1600
#define CHUNK   800                  // MUST stay <= 1024 (10-bit local idx)
#define NTUP    (3 * B * N)          // 6144 tuples
#define CH0     (HW0 / CHUNK)        // 32
#define CH1     (HW1 / CHUNK)        // 8
#define CH2     (HW2 / CHUNK)        // 2
#define NCHUNKS (CH0 + CH1 + CH2)    // 42
#define GBLOCKS (NTUP / 16)          // 384 gather blocks (8 warps x 2 tuples)

// Scratch (no device allocations allowed)
__device__ unsigned long long g_part[NCHUNKS][B][N];  // per-chunk argmin partials
__device__ float        g_blk[3][GBLOCKS];            // per-block loss partials
__device__ unsigned int g_count;                      // last-block ticket (zero-init; reset each run)

// Packed f32x2 ops (sm_103a; ptxas won't auto-fuse -- must be PTX)
#define PACK_F32X2(out, lo, hi) \
    asm("mov.b64 %0, {%1, %2};" : "=l"(out) : "f"(lo), "f"(hi))
#define UNPACK_U32X2(lo, hi, in) \
    asm("mov.b64 {%0, %1}, %2;" : "=r"(lo), "=r"(hi) : "l"(in))
#define ADD_F32X2(out, a, b) \
    asm("add.rn.f32x2 %0, %1, %2;" : "=l"(out) : "l"(a), "l"(b))
#define MUL_F32X2(out, a, b) \
    asm("mul.rn.f32x2 %0, %1, %2;" : "=l"(out) : "l"(a), "l"(b))
#define FMA_F32X2(out, a, b, c) \
    asm("fma.rn.f32x2 %0, %1, %2, %3;" : "=l"(out) : "l"(a), "l"(b), "l"(c))

// ---------------------------------------------------------------------------
// Kernel 1: per-chunk nearest-pred search, no atomics, no init needed.
// Grid (NCHUNKS, B, 2). Block 256 = 32 lanes x 8 rows; each thread holds 8 gts.
// PRED-PACKED f32x2: gxx[i] = (-gx_i, -gx_i) splatted ONCE outside the loop;
// each iteration processes TWO preds packed as (x_p0, x_p1)/(y_p0, y_p1),
// so per-iter pack cost is 2 mov.b64 for 2 preds (was 2 per pred).
// Min-update stays integer: key = (d2_bits & 0xFFFFFC00) | p_local (LOP3),
// kmin = umin(kmin, key) (IMNMX). Tie -> lower p_local = first occurrence.
// Exact d2 is recomputed in gather, so the threshold is unaffected.
// ---------------------------------------------------------------------------
__global__ __launch_bounds__(256)
void argmin_kernel(const float* __restrict__ reg0,
                   const float* __restrict__ reg1,
                   const float* __restrict__ reg2,
                   const float* __restrict__ gt) {
    const int bx = blockIdx.x;   // chunk slot 0..41
    const int b  = blockIdx.y;
    const int gh = blockIdx.z;   // gt half

    int chunk, HW;
    const float* reg;
    if (bx < CH0)            { chunk = bx;               HW = HW0; reg = reg0; }
    else if (bx < CH0 + CH1) { chunk = bx - CH0;         HW = HW1; reg = reg1; }
    else                     { chunk = bx - (CH0 + CH1); HW = HW2; reg = reg2; }

    const int tx = threadIdx.x & 31;
    const int ty = threadIdx.x >> 5;           // 0..7
    const int gbase = gh * 64 + ty * 8;        // first of this thread's 8 gts

    // Splatted negated gt coords: gxx[i] = (-gx_i, -gx_i)
    unsigned long long gxx[8], gyy[8];
    unsigned kmin[8];
    const float* gtb = gt + ((size_t)b * N + gbase) * 4;
#pragma unroll
    for (int i = 0; i < 8; i++) {
        float nx = -gtb[i * 4 + 0];
        float ny = -gtb[i * 4 + 1];
        PACK_F32X2(gxx[i], nx, nx);
        PACK_F32X2(gyy[i], ny, ny);
        kmin[i] = 0xFFFFFFFFu;
    }

    const float* regb = reg + (size_t)b * HW * 4;
    const int pbase = chunk * CHUNK;

    // 12 double-pred iterations (slots 0..23), then 1 single-pred (slot 24).
#pragma unroll 2
    for (int it = 0; it < 12; it++) {
        const int poff = it * 64 + tx;                    // local idx of pred 0
        float4 v0 = *reinterpret_cast<const float4*>(regb + (size_t)(pbase + poff) * 4);
        float4 v1 = *reinterpret_cast<const float4*>(regb + (size_t)(pbase + poff + 32) * 4);
        unsigned long long px2, py2;
        PACK_F32X2(px2, v0.x, v1.x);
        PACK_F32X2(py2, v0.y, v1.y);
        const unsigned pl0 = (unsigned)poff;
        const unsigned pl1 = (unsigned)poff + 32u;
#pragma unroll
        for (int i = 0; i < 8; i++) {
            unsigned long long dx, dy, m, d2v;
            ADD_F32X2(dx, gxx[i], px2);      // (p0x-gx, p1x-gx)
            ADD_F32X2(dy, gyy[i], py2);
            MUL_F32X2(m, dx, dx);
            FMA_F32X2(d2v, dy, dy, m);
            unsigned lo, hi;
            UNPACK_U32X2(lo, hi, d2v);
            kmin[i] = umin(kmin[i], (lo & 0xFFFFFC00u) | pl0);
            kmin[i] = umin(kmin[i], (hi & 0xFFFFFC00u) | pl1);
        }
    }
    {   // tail: slot 24 (preds pbase+768+tx), single pred via duplicated lanes
        const int poff = 768 + tx;
        float4 v0 = *reinterpret_cast<const float4*>(regb + (size_t)(pbase + poff) * 4);
        unsigned long long px2, py2;
        PACK_F32X2(px2, v0.x, v0.x);
        PACK_F32X2(py2, v0.y, v0.y);
        const unsigned pl0 = (unsigned)poff;
#pragma unroll
        for (int i = 0; i < 8; i++) {
            unsigned long long dx, dy, m, d2v;
            ADD_F32X2(dx, gxx[i], px2);
            ADD_F32X2(dy, gyy[i], py2);
            MUL_F32X2(m, dx, dx);
            FMA_F32X2(d2v, dy, dy, m);
            unsigned lo, hi;
            UNPACK_U32X2(lo, hi, d2v);
            kmin[i] = umin(kmin[i], (lo & 0xFFFFFC00u) | pl0);
        }
    }

    // Warp reduce u32 keys; lane 0 writes u64 partial (trunc_d2, global idx).
#pragma unroll
    for (int i = 0; i < 8; i++) {
        unsigned k = kmin[i];
#pragma unroll
        for (int off = 16; off > 0; off >>= 1)
            k = umin(k, __shfl_xor_sync(0xFFFFFFFFu, k, off));
        if (tx == 0) {
            unsigned idx = (unsigned)pbase + (k & 0x3FFu);
            g_part[bx][b][gbase + i] =
                ((unsigned long long)(k & 0xFFFFFC00u) << 32) | idx;
        }
    }
}

// ---------------------------------------------------------------------------
// Kernel 2: fused gather + CE/L1 + full deterministic reduction.
// TWO tuples per warp (doubles MLP on the dependent load chains); 8 warps x
// 2 tuples per block, GBLOCKS=384 blocks. Tuple pairs (2t, 2t+1) never
// straddle a level boundary (2048 is even).
// Recomputes EXACT d2 from reg[id]/gt for the distance threshold.
// Last block (ticket pattern) reduces all block partials and writes outputs.
// ---------------------------------------------------------------------------
__global__ __launch_bounds__(256)
void gather_kernel(const float* __restrict__ cls0,
                   const float* __restrict__ cls1,
                   const float* __restrict__ cls2,
                   const float* __restrict__ reg0,
                   const float* __restrict__ reg1,
                   const float* __restrict__ reg2,
                   const float* __restrict__ gt,
                   const int*   __restrict__ labels,
                   float*       __restrict__ out) {
    const int wib  = threadIdx.x >> 5;                  // warp in block 0..7
    const int lane = threadIdx.x & 31;
    const int w0   = (blockIdx.x * 8 + wib) * 2;        // first tuple id
    // w1 = w0 + 1 -- same level always.

    const int lvl = w0 / (B * N);
    const int r0  = w0 - lvl * (B * N);
    const int r1  = r0 + 1;
    const int b0  = r0 / N, g0 = r0 - b0 * N;
    const int b1  = r1 / N, g1 = r1 - b1 * N;

    const float* cls; const float* reg; int HW, s0, nch;
    if (lvl == 0)      { cls = cls0; reg = reg0; HW = HW0; s0 = 0;         nch = CH0; }
    else if (lvl == 1) { cls = cls1; reg = reg1; HW = HW1; s0 = CH0;       nch = CH1; }
    else               { cls = cls2; reg = reg2; HW = HW2; s0 = CH0 + CH1; nch = CH2; }

    // Min over each tuple's chunk partials (lane c holds chunk c's key).
    unsigned long long keyA = 0xFFFFFFFFFFFFFFFFULL;
    unsigned long long keyB = 0xFFFFFFFFFFFFFFFFULL;
    if (lane < nch) {
        keyA = g_part[s0 + lane][b0][g0];
        keyB = g_part[s0 + lane][b1][g1];
    }
#pragma unroll
    for (int off = 16; off > 0; off >>= 1) {
        unsigned long long a2 = __shfl_xor_sync(0xFFFFFFFFu, keyA, off);
        unsigned long long b2 = __shfl_xor_sync(0xFFFFFFFFu, keyB, off);
        keyA = (a2 < keyA) ? a2 : keyA;
        keyB = (b2 < keyB) ? b2 : keyB;
    }
    const unsigned idA = (unsigned)keyA;
    const unsigned idB = (unsigned)keyB;

    // CE via warp logsumexp over 80 classes, both tuples interleaved.
    const float* crowA = cls + ((size_t)b0 * HW + idA) * NC;
    const float* crowB = cls + ((size_t)b1 * HW + idB) * NC;
    const float NEGINF = -__int_as_float(0x7F800000);
    float a0 = NEGINF, a1 = NEGINF, a2 = NEGINF;
    float c0 = NEGINF, c1 = NEGINF, c2 = NEGINF;
    if (lane < NC)      { a0 = crowA[lane];      c0 = crowB[lane]; }
    if (lane + 32 < NC) { a1 = crowA[lane + 32]; c1 = crowB[lane + 32]; }
    if (lane + 64 < NC) { a2 = crowA[lane + 64]; c2 = crowB[lane + 64]; }
    float mxA = fmaxf(a0, fmaxf(a1, a2));
    float mxB = fmaxf(c0, fmaxf(c1, c2));
#pragma unroll
    for (int off = 16; off > 0; off >>= 1) {
        mxA = fmaxf(mxA, __shfl_xor_sync(0xFFFFFFFFu, mxA, off));
        mxB = fmaxf(mxB, __shfl_xor_sync(0xFFFFFFFFu, mxB, off));
    }
    float smA = 0.0f, smB = 0.0f;
    if (lane < NC)      { smA += expf(a0 - mxA); smB += expf(c0 - mxB); }
    if (lane + 32 < NC) { smA += expf(a1 - mxA); smB += expf(c1 - mxB); }
    if (lane + 64 < NC) { smA += expf(a2 - mxA); smB += expf(c2 - mxB); }
#pragma unroll
    for (int off = 16; off > 0; off >>= 1) {
        smA += __shfl_xor_sync(0xFFFFFFFFu, smA, off);
        smB += __shfl_xor_sync(0xFFFFFFFFu, smB, off);
    }
    float lseA = mxA + logf(smA);
    float lseB = mxB + logf(smB);

    __shared__ float s_ce[8], s_l1[8], s_w[8];
    __shared__ int   s_last;

    if (lane == 0) {
        const float* gtrA = gt + ((size_t)b0 * N + g0) * 4;
        const float* gtrB = gt + ((size_t)b1 * N + g1) * 4;
        const float* rrA  = reg + ((size_t)b0 * HW + idA) * 4;
        const float* rrB  = reg + ((size_t)b1 * HW + idB) * 4;

        float dxA = gtrA[0] - rrA[0], dyA = gtrA[1] - rrA[1];
        float dxB = gtrB[0] - rrB[0], dyB = gtrB[1] - rrB[1];
        float d2A = dxA * dxA + dyA * dyA;
        float d2B = dxB * dxB + dyB * dyB;
        float wA = (sqrtf(d2A) < 2.5f) ? 1.0f : 0.0f;
        float wB = (sqrtf(d2B) < 2.5f) ? 1.0f : 0.0f;

        float ceA = lseA - crowA[labels[b0 * N + g0]];
        float ceB = lseB - crowB[labels[b1 * N + g1]];
        float l1A = fabsf(rrA[0] - gtrA[0]) + fabsf(rrA[1] - gtrA[1]) +
                    fabsf(rrA[2] - gtrA[2]) + fabsf(rrA[3] - gtrA[3]);
        float l1B = fabsf(rrB[0] - gtrB[0]) + fabsf(rrB[1] - gtrB[1]) +
                    fabsf(rrB[2] - gtrB[2]) + fabsf(rrB[3] - gtrB[3]);

        s_ce[wib] = ceA * wA + ceB * wB;
        s_l1[wib] = l1A * wA + l1B * wB;
        s_w[wib]  = wA + wB;
    }
    __syncthreads();

    // Block partials + ticket
    if (threadIdx.x == 0) {
        float a = 0.0f, c = 0.0f, nn = 0.0f;
#pragma unroll
        for (int i = 0; i < 8; i++) { a += s_ce[i]; c += s_l1[i]; nn += s_w[i]; }
        g_blk[0][blockIdx.x] = a;
        g_blk[1][blockIdx.x] = c;
        g_blk[2][blockIdx.x] = nn;
        __threadfence();
        unsigned t = atomicAdd(&g_count, 1u);
        s_last = (t == GBLOCKS - 1);
    }
    __syncthreads();

    if (!s_last) return;

    // Last block: deterministic tree reduction of GBLOCKS partials.
    __shared__ float r0s[256], r1s[256], r2s[256];
    int tid = threadIdx.x;
    float a = 0.0f, c = 0.0f, nn = 0.0f;
    for (int i = tid; i < GBLOCKS; i += 256) {
        a  += g_blk[0][i];
        c  += g_blk[1][i];
        nn += g_blk[2][i];
    }
    r0s[tid] = a; r1s[tid] = c; r2s[tid] = nn;
    __syncthreads();
    for (int off = 128; off > 0; off >>= 1) {
        if (tid < off) {
            r0s[tid] += r0s[tid + off];
            r1s[tid] += r1s[tid + off];
            r2s[tid] += r2s[tid + off];
        }
        __syncthreads();
    }
    if (tid == 0) {
        float np    = r2s[0];
        float denom = fmaxf(np, 1.0f);
        out[0] = r0s[0] / denom;
        out[1] = r1s[0] / denom;
        out[2] = np;
        g_count = 0;   // reset ticket for next graph replay
    }
}

// ---------------------------------------------------------------------------
// Bind inputs BY ELEMENT COUNT (metadata order is interleaved:
// cls_0, reg_0, cls_1, reg_1, cls_2, reg_2, gt, labels). All 8 element
// counts are distinct, so size-based binding is unambiguous.
// ---------------------------------------------------------------------------
extern "C" void kernel_launch(void* const* d_in, const int* in_sizes, int n_in,
                              void* d_out, int out_size) {
    const float* cls0 = 0; const float* cls1 = 0; const float* cls2 = 0;
    const float* reg0 = 0; const float* reg1 = 0; const float* reg2 = 0;
    const float* gt   = 0; const int*   lab  = 0;

    for (int i = 0; i < n_in; i++) {
        switch (in_sizes[i]) {
            case B * HW0 * NC: cls0 = (const float*)d_in[i]; break;  // 32,768,000
            case B * HW1 * NC: cls1 = (const float*)d_in[i]; break;  //  8,192,000
            case B * HW2 * NC: cls2 = (const float*)d_in[i]; break;  //  2,048,000
            case B * HW0 * 4:  reg0 = (const float*)d_in[i]; break;  //  1,638,400
            case B * HW1 * 4:  reg1 = (const float*)d_in[i]; break;  //    409,600
            case B * HW2 * 4:  reg2 = (const float*)d_in[i]; break;  //    102,400
            case B * N * 4:    gt   = (const float*)d_in[i]; break;  //      8,192
            case B * N:        lab  = (const int*)d_in[i];   break;  //      2,048
        }
    }

    dim3 grid(NCHUNKS, B, 2);
    argmin_kernel<<<grid, 256>>>(reg0, reg1, reg2, gt);

    gather_kernel<<<GBLOCKS, 256>>>(cls0, cls1, cls2, reg0, reg1, reg2, gt, lab,
                                    (float*)d_out);
}

// round 11
// speedup vs baseline: 1.1567x; 1.1567x over previous
#include <cuda_runtime.h>
#include <math.h>

#define B       16
#define N       128
#define NC      80
#define HW0     25600
#define HW1     6400
#define HW2     1600
#define CHUNK   800                  // MUST stay <= 1024 (10-bit local idx)
#define NTUP    (3 * B * N)          // 6144 tuples
#define CH0     (HW0 / CHUNK)        // 32
#define CH1     (HW1 / CHUNK)        // 8
#define CH2     (HW2 / CHUNK)        // 2
#define NCHUNKS (CH0 + CH1 + CH2)    // 42
#define GBLOCKS (NTUP / 16)          // 384 gather blocks (8 warps x 2 tuples)

// Scratch (no device allocations allowed).
// g_part TRANSPOSED to [B][N][chunk]: gather's 32-lane key load is ~2 cache
// lines (contiguous) instead of 32 lines at a 16KB stride.
__device__ unsigned long long g_part[B][N][NCHUNKS];
__device__ float        g_blk[3][GBLOCKS];            // per-block loss partials
__device__ unsigned int g_count;                      // last-block ticket (zero-init; reset each run)

// Packed f32x2 ops (sm_103a; ptxas won't auto-fuse -- must be PTX)
#define PACK_F32X2(out, lo, hi) \
    asm("mov.b64 %0, {%1, %2};" : "=l"(out) : "f"(lo), "f"(hi))
#define UNPACK_U32X2(lo, hi, in) \
    asm("mov.b64 {%0, %1}, %2;" : "=r"(lo), "=r"(hi) : "l"(in))
#define ADD_F32X2(out, a, b) \
    asm("add.rn.f32x2 %0, %1, %2;" : "=l"(out) : "l"(a), "l"(b))
#define MUL_F32X2(out, a, b) \
    asm("mul.rn.f32x2 %0, %1, %2;" : "=l"(out) : "l"(a), "l"(b))
#define FMA_F32X2(out, a, b, c) \
    asm("fma.rn.f32x2 %0, %1, %2, %3;" : "=l"(out) : "l"(a), "l"(b), "l"(c))

// ---------------------------------------------------------------------------
// Kernel 1: per-chunk nearest-pred search (R8 form -- known-good ~17us).
// Grid (NCHUNKS, B, 2). Block 256 = 32 lanes x 8 rows; each thread holds 8 gts
// (gt coords packed 2/f32x2). Min-update integer:
//   key = (d2_bits & 0xFFFFFC00) | p_local   (LOP3)
//   kmin = umin(kmin, key)                   (IMNMX)
// d2>=0 -> float bits monotone as uint; truncation 2^-13 relative; tie ->
// lower p_local = first occurrence. Exact d2 recomputed in gather.
// ---------------------------------------------------------------------------
__global__ __launch_bounds__(256)
void argmin_kernel(const float* __restrict__ reg0,
                   const float* __restrict__ reg1,
                   const float* __restrict__ reg2,
                   const float* __restrict__ gt) {
    const int bx = blockIdx.x;   // chunk slot 0..41
    const int b  = blockIdx.y;
    const int gh = blockIdx.z;   // gt half

    int chunk, HW;
    const float* reg;
    if (bx < CH0)            { chunk = bx;               HW = HW0; reg = reg0; }
    else if (bx < CH0 + CH1) { chunk = bx - CH0;         HW = HW1; reg = reg1; }
    else                     { chunk = bx - (CH0 + CH1); HW = HW2; reg = reg2; }

    const int tx = threadIdx.x & 31;
    const int ty = threadIdx.x >> 5;           // 0..7
    const int gbase = gh * 64 + ty * 8;        // first of this thread's 8 gts

    // Pre-negated, packed gt coords: gnx[j] = (-gx[2j], -gx[2j+1])
    unsigned long long gnx[4], gny[4];
    unsigned kmin[8];
    const float* gtb = gt + ((size_t)b * N + gbase) * 4;
#pragma unroll
    for (int j = 0; j < 4; j++) {
        float a0 = -gtb[(2 * j    ) * 4 + 0];
        float a1 = -gtb[(2 * j + 1) * 4 + 0];
        float b0 = -gtb[(2 * j    ) * 4 + 1];
        float b1 = -gtb[(2 * j + 1) * 4 + 1];
        PACK_F32X2(gnx[j], a0, a1);
        PACK_F32X2(gny[j], b0, b1);
    }
#pragma unroll
    for (int i = 0; i < 8; i++) kmin[i] = 0xFFFFFFFFu;

    const float* regb = reg + (size_t)b * HW * 4;
    const int pbase = chunk * CHUNK;
    const int pend  = pbase + CHUNK;

    unsigned plocal = tx;
#pragma unroll 5
    for (int p = pbase + tx; p < pend; p += 32, plocal += 32) {
        float4 v = *reinterpret_cast<const float4*>(regb + (size_t)p * 4);
        unsigned long long pxx, pyy;
        PACK_F32X2(pxx, v.x, v.x);
        PACK_F32X2(pyy, v.y, v.y);
#pragma unroll
        for (int j = 0; j < 4; j++) {
            unsigned long long dx2, dy2, m, d2v;
            ADD_F32X2(dx2, gnx[j], pxx);     // (px-gx, px-gx')
            ADD_F32X2(dy2, gny[j], pyy);
            MUL_F32X2(m, dx2, dx2);
            FMA_F32X2(d2v, dy2, dy2, m);
            unsigned lo, hi;
            UNPACK_U32X2(lo, hi, d2v);
            unsigned k0 = (lo & 0xFFFFFC00u) | plocal;   // LOP3
            unsigned k1 = (hi & 0xFFFFFC00u) | plocal;
            kmin[2 * j]     = umin(kmin[2 * j],     k0); // IMNMX
            kmin[2 * j + 1] = umin(kmin[2 * j + 1], k1);
        }
    }

    // Warp reduce u32 keys; lane 0 writes u64 partial (trunc_d2, global idx).
#pragma unroll
    for (int i = 0; i < 8; i++) {
        unsigned k = kmin[i];
#pragma unroll
        for (int off = 16; off > 0; off >>= 1)
            k = umin(k, __shfl_xor_sync(0xFFFFFFFFu, k, off));
        if (tx == 0) {
            unsigned idx = (unsigned)pbase + (k & 0x3FFu);
            g_part[b][gbase + i][bx] =
                ((unsigned long long)(k & 0xFFFFFC00u) << 32) | idx;
        }
    }
}

// ---------------------------------------------------------------------------
// Kernel 2: fused gather + CE/L1 + full deterministic reduction.
// TWO tuples per warp (proven MLP win); 8 warps/block, 384 blocks.
// Scalar loads (gt row, reg row, label, label-logit) issued RIGHT AFTER the
// argmin id is known so their DRAM latency overlaps the logsumexp reductions.
// Warp reductions via shfl trees (sm_103 has no redux.f32).
// Recomputes EXACT d2 for the distance threshold.
// Last block (ticket) reduces all block partials and writes outputs.
// ---------------------------------------------------------------------------
__global__ __launch_bounds__(256)
void gather_kernel(const float* __restrict__ cls0,
                   const float* __restrict__ cls1,
                   const float* __restrict__ cls2,
                   const float* __restrict__ reg0,
                   const float* __restrict__ reg1,
                   const float* __restrict__ reg2,
                   const float* __restrict__ gt,
                   const int*   __restrict__ labels,
                   float*       __restrict__ out) {
    const int wib  = threadIdx.x >> 5;                  // warp in block 0..7
    const int lane = threadIdx.x & 31;
    const int w0   = (blockIdx.x * 8 + wib) * 2;        // first tuple id
    // w1 = w0 + 1 -- same level always (level boundary 2048 is even).

    const int lvl = w0 / (B * N);
    const int r0  = w0 - lvl * (B * N);
    const int r1  = r0 + 1;
    const int b0  = r0 / N, g0 = r0 - b0 * N;
    const int b1  = r1 / N, g1 = r1 - b1 * N;

    const float* cls; const float* reg; int HW, s0, nch;
    if (lvl == 0)      { cls = cls0; reg = reg0; HW = HW0; s0 = 0;         nch = CH0; }
    else if (lvl == 1) { cls = cls1; reg = reg1; HW = HW1; s0 = CH0;       nch = CH1; }
    else               { cls = cls2; reg = reg2; HW = HW2; s0 = CH0 + CH1; nch = CH2; }

    // Min over each tuple's chunk partials (contiguous in transposed g_part).
    unsigned long long keyA = 0xFFFFFFFFFFFFFFFFULL;
    unsigned long long keyB = 0xFFFFFFFFFFFFFFFFULL;
    if (lane < nch) {
        keyA = g_part[b0][g0][s0 + lane];
        keyB = g_part[b1][g1][s0 + lane];
    }
#pragma unroll
    for (int off = 16; off > 0; off >>= 1) {
        unsigned long long a2 = __shfl_xor_sync(0xFFFFFFFFu, keyA, off);
        unsigned long long b2 = __shfl_xor_sync(0xFFFFFFFFu, keyB, off);
        keyA = (a2 < keyA) ? a2 : keyA;
        keyB = (b2 < keyB) ? b2 : keyB;
    }
    const unsigned idA = (unsigned)keyA;
    const unsigned idB = (unsigned)keyB;

    // ---- Issue ALL dependent scalar loads now (uniform addresses ->
    // broadcast-coalesced); consumed after the reductions below. ----
    const float* crowA = cls + ((size_t)b0 * HW + idA) * NC;
    const float* crowB = cls + ((size_t)b1 * HW + idB) * NC;
    const float* gtrA  = gt + ((size_t)b0 * N + g0) * 4;
    const float* gtrB  = gt + ((size_t)b1 * N + g1) * 4;
    const float* rrA   = reg + ((size_t)b0 * HW + idA) * 4;
    const float* rrB   = reg + ((size_t)b1 * HW + idB) * 4;
    float4 gA = *reinterpret_cast<const float4*>(gtrA);
    float4 gB = *reinterpret_cast<const float4*>(gtrB);
    float4 rA = *reinterpret_cast<const float4*>(rrA);
    float4 rB = *reinterpret_cast<const float4*>(rrB);
    int labA = labels[b0 * N + g0];
    int labB = labels[b1 * N + g1];
    float logitA = crowA[labA];
    float logitB = crowB[labB];

    // CE via warp logsumexp over 80 classes, both tuples interleaved.
    const float NEGINF = -__int_as_float(0x7F800000);
    float a0 = NEGINF, a1 = NEGINF, a2v = NEGINF;
    float c0 = NEGINF, c1 = NEGINF, c2v = NEGINF;
    if (lane < NC)      { a0  = crowA[lane];      c0  = crowB[lane]; }
    if (lane + 32 < NC) { a1  = crowA[lane + 32]; c1  = crowB[lane + 32]; }
    if (lane + 64 < NC) { a2v = crowA[lane + 64]; c2v = crowB[lane + 64]; }
    float mxA = fmaxf(a0, fmaxf(a1, a2v));
    float mxB = fmaxf(c0, fmaxf(c1, c2v));
#pragma unroll
    for (int off = 16; off > 0; off >>= 1) {
        mxA = fmaxf(mxA, __shfl_xor_sync(0xFFFFFFFFu, mxA, off));
        mxB = fmaxf(mxB, __shfl_xor_sync(0xFFFFFFFFu, mxB, off));
    }
    float smA = 0.0f, smB = 0.0f;
    if (lane < NC)      { smA += expf(a0  - mxA); smB += expf(c0  - mxB); }
    if (lane + 32 < NC) { smA += expf(a1  - mxA); smB += expf(c1  - mxB); }
    if (lane + 64 < NC) { smA += expf(a2v - mxA); smB += expf(c2v - mxB); }
#pragma unroll
    for (int off = 16; off > 0; off >>= 1) {
        smA += __shfl_xor_sync(0xFFFFFFFFu, smA, off);
        smB += __shfl_xor_sync(0xFFFFFFFFu, smB, off);
    }
    float lseA = mxA + logf(smA);
    float lseB = mxB + logf(smB);

    __shared__ float s_ce[8], s_l1[8], s_w[8];
    __shared__ int   s_last;

    if (lane == 0) {
        float dxA = gA.x - rA.x, dyA = gA.y - rA.y;
        float dxB = gB.x - rB.x, dyB = gB.y - rB.y;
        float d2A = dxA * dxA + dyA * dyA;
        float d2B = dxB * dxB + dyB * dyB;
        float wA = (sqrtf(d2A) < 2.5f) ? 1.0f : 0.0f;
        float wB = (sqrtf(d2B) < 2.5f) ? 1.0f : 0.0f;

        float ceA = lseA - logitA;
        float ceB = lseB - logitB;
        float l1A = fabsf(rA.x - gA.x) + fabsf(rA.y - gA.y) +
                    fabsf(rA.z - gA.z) + fabsf(rA.w - gA.w);
        float l1B = fabsf(rB.x - gB.x) + fabsf(rB.y - gB.y) +
                    fabsf(rB.z - gB.z) + fabsf(rB.w - gB.w);

        s_ce[wib] = ceA * wA + ceB * wB;
        s_l1[wib] = l1A * wA + l1B * wB;
        s_w[wib]  = wA + wB;
    }
    __syncthreads();

    // Block partials + ticket
    if (threadIdx.x == 0) {
        float a = 0.0f, c = 0.0f, nn = 0.0f;
#pragma unroll
        for (int i = 0; i < 8; i++) { a += s_ce[i]; c += s_l1[i]; nn += s_w[i]; }
        g_blk[0][blockIdx.x] = a;
        g_blk[1][blockIdx.x] = c;
        g_blk[2][blockIdx.x] = nn;
        __threadfence();
        unsigned t = atomicAdd(&g_count, 1u);
        s_last = (t == GBLOCKS - 1);
    }
    __syncthreads();

    if (!s_last) return;

    // Last block: deterministic tree reduction of GBLOCKS partials.
    __shared__ float r0s[256], r1s[256], r2s[256];
    int tid = threadIdx.x;
    float a = 0.0f, c = 0.0f, nn = 0.0f;
    for (int i = tid; i < GBLOCKS; i += 256) {
        a  += g_blk[0][i];
        c  += g_blk[1][i];
        nn += g_blk[2][i];
    }
    r0s[tid] = a; r1s[tid] = c; r2s[tid] = nn;
    __syncthreads();
    for (int off = 128; off > 0; off >>= 1) {
        if (tid < off) {
            r0s[tid] += r0s[tid + off];
            r1s[tid] += r1s[tid + off];
            r2s[tid] += r2s[tid + off];
        }
        __syncthreads();
    }
    if (tid == 0) {
        float np    = r2s[0];
        float denom = fmaxf(np, 1.0f);
        out[0] = r0s[0] / denom;
        out[1] = r1s[0] / denom;
        out[2] = np;
        g_count = 0;   // reset ticket for next graph replay
    }
}

// ---------------------------------------------------------------------------
// Bind inputs BY ELEMENT COUNT (metadata order is interleaved:
// cls_0, reg_0, cls_1, reg_1, cls_2, reg_2, gt, labels). All 8 element
// counts are distinct, so size-based binding is unambiguous.
// ---------------------------------------------------------------------------
extern "C" void kernel_launch(void* const* d_in, const int* in_sizes, int n_in,
                              void* d_out, int out_size) {
    const float* cls0 = 0; const float* cls1 = 0; const float* cls2 = 0;
    const float* reg0 = 0; const float* reg1 = 0; const float* reg2 = 0;
    const float* gt   = 0; const int*   lab  = 0;

    for (int i = 0; i < n_in; i++) {
        switch (in_sizes[i]) {
            case B * HW0 * NC: cls0 = (const float*)d_in[i]; break;  // 32,768,000
            case B * HW1 * NC: cls1 = (const float*)d_in[i]; break;  //  8,192,000
            case B * HW2 * NC: cls2 = (const float*)d_in[i]; break;  //  2,048,000
            case B * HW0 * 4:  reg0 = (const float*)d_in[i]; break;  //  1,638,400
            case B * HW1 * 4:  reg1 = (const float*)d_in[i]; break;  //    409,600
            case B * HW2 * 4:  reg2 = (const float*)d_in[i]; break;  //    102,400
            case B * N * 4:    gt   = (const float*)d_in[i]; break;  //      8,192
            case B * N:        lab  = (const int*)d_in[i];   break;  //      2,048
        }
    }

    dim3 grid(NCHUNKS, B, 2);
    argmin_kernel<<<grid, 256>>>(reg0, reg1, reg2, gt);

    gather_kernel<<<GBLOCKS, 256>>>(cls0, cls1, cls2, reg0, reg1, reg2, gt, lab,
                                    (float*)d_out);
}